// round 16
// baseline (speedup 1.0000x reference)
#include <cuda_runtime.h>
#include <cstdint>

// Problem constants
#define NN    4096
#define RR    4
#define LL    8
#define HH    64
#define CC    16
#define FF    64
#define FEAT  144            // FF + HH + CC
#define NPAIR (RR*NN)        // 16384

// Candidate filter: bits >= B0  <=>  g >= ~5.6999
// Excluded elements provably have v = lg + g < 5.69994 + 0.0011 < VSAFE.
#define B0_BITS 4280621056u          // 8360588u << 9
#define VSAFE   5.705f

// Device scratch (static data: no runtime allocation)
__device__ int      g_walk[LL][NPAIR];    // un-flipped walk nodes: [t][r*N+n]
__device__ uint32_t g_one = 1u;           // runtime 1: adds -> IMAD (FMA pipe)
__device__ uint32_t g_rotm[2] = {1u << 13, 1u << 15};  // runtime rot multipliers

struct Keys { uint32_t k1[LL], k2[LL]; };

// ---------------------------------------------------------------------------
// Threefry-2x32, 20 rounds — canonical, matches JAX's threefry2x32 primitive.
// tf_bal: pipe-balanced form.
//   - adds via IMAD with runtime 1 (FMA pipe)
//   - rotations r=13, r=15 (3x each) via IMAD.WIDE + 3-input LOP3 (FMA pipe)
//   - remaining rotations via SHF (ALU pipe)
//   ALU ~37 / FMA ~37 per element -> issue-bound instead of ALU-bound.
// tf_plain: plain form for the rare exact-refine path. Identical bits.
// ---------------------------------------------------------------------------
#define RS(r) { x0 += x1; x1 = __funnelshift_l(x1, x1, (r)) ^ x0; }

__device__ __forceinline__ uint32_t tf_bal(uint32_t ctr, uint32_t one,
    uint32_t m13, uint32_t m15,
    uint32_t k1, uint32_t k2, uint32_t k3,
    uint32_t k31, uint32_t k12, uint32_t k23, uint32_t k34, uint32_t k15) {
#define RADD(a,b) ((a) * one + (b))
#define RNDS(r) { x0 = RADD(x1, x0); x1 = __funnelshift_l(x1, x1, (r)) ^ x0; }
#define RNDW(m) { x0 = RADD(x1, x0); \
                  unsigned long long tt = (unsigned long long)x1 * (m); \
                  x1 = ((uint32_t)tt | (uint32_t)(tt >> 32)) ^ x0; }
  uint32_t x0 = k1, x1 = RADD(ctr, k2);
  RNDW(m13) RNDW(m15) RNDS(26) RNDS(6)
  x0 = RADD(k2, x0); x1 = RADD(k31, x1);
  RNDS(17) RNDS(29) RNDS(16) RNDS(24)
  x0 = RADD(k3, x0); x1 = RADD(k12, x1);
  RNDW(m13) RNDW(m15) RNDS(26) RNDS(6)
  x0 = RADD(k1, x0); x1 = RADD(k23, x1);
  RNDS(17) RNDS(29) RNDS(16) RNDS(24)
  x0 = RADD(k2, x0); x1 = RADD(k34, x1);
  RNDW(m13) RNDW(m15) RNDS(26) RNDS(6)
  x0 = RADD(k3, x0); x1 = RADD(k15, x1);
#undef RNDW
#undef RNDS
#undef RADD
  return x0 ^ x1;
}

__device__ uint32_t tf_plain(uint32_t ctr, uint32_t k1, uint32_t k2, uint32_t k3) {
  uint32_t x0 = k1, x1 = ctr + k2;
  RS(13) RS(15) RS(26) RS(6)
  x0 += k2; x1 += k3 + 1u;
  RS(17) RS(29) RS(16) RS(24)
  x0 += k3; x1 += k1 + 2u;
  RS(13) RS(15) RS(26) RS(6)
  x0 += k1; x1 += k2 + 3u;
  RS(17) RS(29) RS(16) RS(24)
  x0 += k2; x1 += k3 + 4u;
  RS(13) RS(15) RS(26) RS(6)
  x0 += k3; x1 += k1 + 5u;
  return x0 ^ x1;
}

static void host_threefry(uint32_t k1, uint32_t k2, uint32_t& x0, uint32_t& x1) {
  uint32_t k3 = k1 ^ k2 ^ 0x1BD11BDAu;
  x0 += k1; x1 += k2;
#define TFRH(r) { x0 += x1; x1 = (x1 << (r)) | (x1 >> (32 - (r))); x1 ^= x0; }
  TFRH(13) TFRH(15) TFRH(26) TFRH(6)
  x0 += k2; x1 += k3 + 1u;
  TFRH(17) TFRH(29) TFRH(16) TFRH(24)
  x0 += k3; x1 += k1 + 2u;
  TFRH(13) TFRH(15) TFRH(26) TFRH(6)
  x0 += k1; x1 += k2 + 3u;
  TFRH(17) TFRH(29) TFRH(16) TFRH(24)
  x0 += k2; x1 += k3 + 4u;
  TFRH(13) TFRH(15) TFRH(26) TFRH(6)
  x0 += k3; x1 += k1 + 5u;
#undef TFRH
}

__device__ __forceinline__ float sigmoidf_(float x) {
  if (x >= 0.f) { float z = expf(-x); return 1.f / (1.f + z); }
  float z = expf(x); return z / (1.f + z);
}

// Exact reference value, byte-identical to the validated pipeline:
//   v = log(p + 1e-9) + (-log(-log(max(tiny, f))))
__device__ __noinline__ float refine_v(uint32_t ctr, float pj,
                                       uint32_t k1, uint32_t k2, uint32_t k3) {
  uint32_t bits = tf_plain(ctr, k1, k2, k3);
  float f = __uint_as_float((bits >> 9) | 0x3f800000u) - 1.0f;
  float u = fmaxf(1.17549435e-38f, f);
  float g = -logf(-logf(u));
  return logf(pj + 1e-9f) + g;
}

// Block-wide argmax with first-index tie rule (fallback path only).
__device__ __forceinline__ void block_argmax(float bv, int bj, int tid,
                                             float* sv, int* sj,
                                             float* s_bv, int* s_bj) {
  for (int off = 16; off; off >>= 1) {
    float ov = __shfl_down_sync(0xffffffffu, bv, off);
    int   oj = __shfl_down_sync(0xffffffffu, bj, off);
    if (ov > bv || (ov == bv && oj < bj)) { bv = ov; bj = oj; }
  }
  __syncthreads();
  if ((tid & 31) == 0) { sv[tid >> 5] = bv; sj[tid >> 5] = bj; }
  __syncthreads();
  if (tid == 0) {
    float xb = sv[0]; int xj = sj[0];
    for (int w = 1; w < 8; w++)
      if (sv[w] > xb || (sv[w] == xb && sj[w] < xj)) { xb = sv[w]; xj = sj[w]; }
    *s_bv = xb; *s_bj = xj;
  }
  __syncthreads();
}

// ---------------------------------------------------------------------------
// Fused walk kernel: one block per (r,n) pair runs all 7 Gumbel-max steps.
// Pass 1: Threefry (pipe-balanced) + integer threshold.
// Pass 2: warp 0 only — exact refine of <=64 compacted candidates.
// ---------------------------------------------------------------------------
__global__ void __launch_bounds__(256) walk_all_kernel(
    const float* __restrict__ prob, Keys ks) {
  __shared__ float sv[8];
  __shared__ int   sj[8];
  __shared__ float s_bv;
  __shared__ int   s_bj;
  __shared__ int   s_cnt;
  __shared__ int   s_cand[64];

  const uint32_t one = g_one;
  const uint32_t m13 = g_rotm[0], m15 = g_rotm[1];

  int p   = blockIdx.x;                  // r*N + n
  int tid = threadIdx.x;
  uint32_t base = (uint32_t)p << 12;     // p * NN
  int cur = p & (NN - 1);
  if (tid == 0) g_walk[0][p] = cur;

  for (int t = 1; t < LL; t++) {
    uint32_t k1 = ks.k1[t], k2 = ks.k2[t];
    uint32_t k3  = k1 ^ k2 ^ 0x1BD11BDAu;
    uint32_t k31 = k3 + 1u, k12 = k1 + 2u, k23 = k2 + 3u,
             k34 = k3 + 4u, k15 = k1 + 5u;
    const float* __restrict__ row = prob + (size_t)cur * NN;

    if (tid == 0) s_cnt = 0;
    __syncthreads();

    // Pass 1: Threefry + integer threshold. Candidate rate ~0.33%.
    uint32_t c0 = base + (uint32_t)tid;
#pragma unroll 4
    for (int g = 0; g < NN / 256; g++) {
      uint32_t bits = tf_bal(c0 + (uint32_t)(g * 256), one, m13, m15,
                             k1, k2, k3, k31, k12, k23, k34, k15);
      if (bits >= B0_BITS) {
        int slot = atomicAdd(&s_cnt, 1);
        if (slot < 64) s_cand[slot] = g * 256 + tid;
      }
    }
    __syncthreads();

    // Pass 2: warp 0 refines the compacted candidates (typically ~14).
    int ncand = s_cnt;
    if (tid < 32) {
      float bv = __int_as_float(0xff800000);   // -inf
      int   bj = 0x7fffffff;
      int nc = ncand < 64 ? ncand : 64;
      for (int s = tid; s < nc; s += 32) {
        int j = s_cand[s];
        float v = refine_v(base + (uint32_t)j, __ldg(row + j), k1, k2, k3);
        if (v > bv || (v == bv && j < bj)) { bv = v; bj = j; }
      }
      for (int off = 16; off; off >>= 1) {
        float ov = __shfl_down_sync(0xffffffffu, bv, off);
        int   oj = __shfl_down_sync(0xffffffffu, bj, off);
        if (ov > bv || (ov == bv && oj < bj)) { bv = ov; bj = oj; }
      }
      if (tid == 0) { s_bv = bv; s_bj = bj; }
    }
    __syncthreads();

    // Safety fallback: exact full-row scan (rare: ~0.1% of rows).
    if (ncand > 64 || !(s_bv >= VSAFE)) {
      float bv = __int_as_float(0xff800000);
      int   bj = 0x7fffffff;
#pragma unroll 4
      for (int g = 0; g < NN / 256; g++) {
        int j = g * 256 + tid;
        float v = refine_v(base + (uint32_t)j, __ldg(row + j), k1, k2, k3);
        if (v > bv || (v == bv && j < bj)) { bv = v; bj = j; }
      }
      block_argmax(bv, bj, tid, sv, sj, &s_bv, &s_bj);
    }

    cur = s_bj;
    if (tid == 0) g_walk[t][p] = cur;
    __syncthreads();
  }
}

// ---------------------------------------------------------------------------
// Trajectory recurrence: 4 warps/block (128 thr), 4 pairs per warp, grid 1024.
// Weights via __ldg (L1-resident broadcast). Bit-identical accumulation order.
// ---------------------------------------------------------------------------
__global__ void __launch_bounds__(128) rye_kernel(
    const float* __restrict__ inv_in, const float* __restrict__ eq_in,
    const float* __restrict__ W1, const float* __restrict__ b1,
    const float* __restrict__ W2, const float* __restrict__ b2,
    float* __restrict__ out) {
  __shared__ __align__(16) float sfT_all[4][FEAT * 4];   // [warp][k][p]
  __shared__ float seqh_all[4][192];                     // [warp][p][d*16+c]
  __shared__ float scoef_all[4][128];                    // [warp][p][o]
  __shared__ float seqin_all[4][16];                     // [warp][p][d]

  int tid  = threadIdx.x;
  int w    = tid >> 5;
  int lane = tid & 31;

  float* sfT   = sfT_all[w];
  float* seqh  = seqh_all[w];
  float* scoef = scoef_all[w];
  float* seqin = seqin_all[w];

  int pair0 = blockIdx.x * 16 + w * 4;

  for (int i = lane; i < 256; i += 32) sfT[256 + i] = 0.f;
  for (int i = lane; i < 192; i += 32) seqh[i] = 0.f;
  __syncwarp();

  const float bb0 = __ldg(b1 + lane);
  const float bb1 = __ldg(b1 + 32 + lane);
  const float b2v = __ldg(b2 + lane);

  const size_t EQ_BASE = (size_t)RR * LL * NN * HH;   // 8388608
  const int pl = lane & 3;
  const int kk = lane >> 2;

  for (int l = 0; l < LL; l++) {
    int nd = (lane < 4) ? g_walk[LL - 1 - l][pair0 + lane] : 0;
    int np = __shfl_sync(0xffffffffu, nd, pl);

#pragma unroll
    for (int j = 0; j < 8; j++) {
      int k = kk + 8 * j;
      sfT[4 * k + pl] = __ldg(inv_in + (size_t)np * FF + k);
    }
    if (lane < 12) {
      float e = 0.f;
      if (l > 0) {
        int prev = g_walk[LL - l][pair0 + pl];
        e = __ldg(eq_in + (size_t)np * 3 + kk) - __ldg(eq_in + (size_t)prev * 3 + kk);
      }
      seqin[pl * 4 + kk] = e;
    }
    if (lane < 16) {
#pragma unroll
      for (int p = 0; p < 4; p++) {
        float d0 = seqh[p * 48 + lane], d1 = seqh[p * 48 + 16 + lane],
              d2 = seqh[p * 48 + 32 + lane];
        sfT[4 * (128 + lane) + p] = d0 * d0 + d1 * d1 + d2 * d2;
      }
    }
    __syncwarp();

    float a00 = 0.f, a01 = 0.f, a02 = 0.f, a03 = 0.f;
    float a10 = 0.f, a11 = 0.f, a12 = 0.f, a13 = 0.f;
#pragma unroll 4
    for (int k = 0; k < FEAT; k++) {
      float w0 = __ldg(W1 + k * HH + lane);
      float w1 = __ldg(W1 + k * HH + 32 + lane);
      float4 f = *(const float4*)(sfT + 4 * k);
      a00 = fmaf(f.x, w0, a00); a10 = fmaf(f.x, w1, a10);
      a01 = fmaf(f.y, w0, a01); a11 = fmaf(f.y, w1, a11);
      a02 = fmaf(f.z, w0, a02); a12 = fmaf(f.z, w1, a12);
      a03 = fmaf(f.w, w0, a03); a13 = fmaf(f.w, w1, a13);
    }
    float H0[4], H1[4];
    H0[0] = tanhf(a00 + bb0); H0[1] = tanhf(a01 + bb0);
    H0[2] = tanhf(a02 + bb0); H0[3] = tanhf(a03 + bb0);
    H1[0] = tanhf(a10 + bb1); H1[1] = tanhf(a11 + bb1);
    H1[2] = tanhf(a12 + bb1); H1[3] = tanhf(a13 + bb1);
    __syncwarp();
    *(float4*)(sfT + 4 * (64 + lane)) = make_float4(H0[0], H0[1], H0[2], H0[3]);
    *(float4*)(sfT + 4 * (96 + lane)) = make_float4(H1[0], H1[1], H1[2], H1[3]);
    __syncwarp();

    float c0 = 0.f, c1 = 0.f, c2 = 0.f, c3 = 0.f;
#pragma unroll 8
    for (int k = 0; k < HH; k++) {
      float wv = __ldg(W2 + k * (2 * CC) + lane);
      float4 h = *(const float4*)(sfT + 4 * (64 + k));
      c0 = fmaf(h.x, wv, c0); c1 = fmaf(h.y, wv, c1);
      c2 = fmaf(h.z, wv, c2); c3 = fmaf(h.w, wv, c3);
    }
    scoef[lane]      = c0 + b2v;
    scoef[32 + lane] = c1 + b2v;
    scoef[64 + lane] = c2 + b2v;
    scoef[96 + lane] = c3 + b2v;
    __syncwarp();

#pragma unroll
    for (int p = 0; p < 4; p++) {
      int pr = pair0 + p; int r = pr >> 12; int n = pr & (NN - 1);
      size_t inv_off = (((size_t)r * LL + l) * NN + n) * HH;
      out[inv_off + lane]      = H0[p];
      out[inv_off + 32 + lane] = H1[p];
    }
    if (lane < 16) {
#pragma unroll
      for (int p = 0; p < 4; p++) {
        float gate = sigmoidf_(scoef[p * 32 + lane]);
        float scl  = scoef[p * 32 + 16 + lane];
        float e0 = seqin[p * 4 + 0], e1 = seqin[p * 4 + 1], e2 = seqin[p * 4 + 2];
        float v0 = seqh[p * 48 + lane]      * gate + e0 * scl;
        float v1 = seqh[p * 48 + 16 + lane] * gate + e1 * scl;
        float v2 = seqh[p * 48 + 32 + lane] * gate + e2 * scl;
        seqh[p * 48 + lane] = v0; seqh[p * 48 + 16 + lane] = v1; seqh[p * 48 + 32 + lane] = v2;
        int pr = pair0 + p; int r = pr >> 12; int n = pr & (NN - 1);
        size_t eq_off = EQ_BASE + (((size_t)r * LL + l) * NN + n) * (3 * CC) + lane;
        out[eq_off]          = v0;
        out[eq_off + CC]     = v1;
        out[eq_off + 2 * CC] = v2;
      }
    }
    __syncwarp();
  }
}

// ---------------------------------------------------------------------------
extern "C" void kernel_launch(void* const* d_in, const int* in_sizes, int n_in,
                              void* d_out, int out_size) {
  const float* prob = (const float*)d_in[0];
  const float* inv  = (const float*)d_in[1];
  const float* eq   = (const float*)d_in[2];
  const float* W1   = (const float*)d_in[3];
  const float* b1   = (const float*)d_in[4];
  const float* W2   = (const float*)d_in[5];
  const float* b2   = (const float*)d_in[6];
  float* out = (float*)d_out;
  (void)in_sizes; (void)n_in; (void)out_size;

  // Step keys: subkey[t] = threefry2x32((0,42), (0, t-1))
  Keys ks;
  for (int t = 1; t < LL; t++) {
    uint32_t x0 = 0u, x1 = (uint32_t)(t - 1);
    host_threefry(0u, 42u, x0, x1);
    ks.k1[t] = x0; ks.k2[t] = x1;
  }
  ks.k1[0] = 0; ks.k2[0] = 0;

  walk_all_kernel<<<NPAIR, 256>>>(prob, ks);
  rye_kernel<<<NPAIR / 16, 128>>>(inv, eq, W1, b1, W2, b2, out);
}

// round 17
// speedup vs baseline: 1.8076x; 1.8076x over previous
#include <cuda_runtime.h>
#include <cstdint>

// Problem constants
#define NN    4096
#define RR    4
#define LL    8
#define HH    64
#define CC    16
#define FF    64
#define FEAT  144            // FF + HH + CC
#define NPAIR (RR*NN)        // 16384

// Candidate filter: bits >= B0  <=>  g >= ~5.6999
// Excluded elements provably have v = lg + g < 5.69994 + 0.0011 < VSAFE.
#define B0_BITS 4280621056u          // 8360588u << 9
#define VSAFE   5.705f

// Device scratch (static data: no runtime allocation)
__device__ int      g_walk[LL][NPAIR];    // un-flipped walk nodes: [t][r*N+n]
__device__ uint32_t g_one = 1u;           // runtime 1: adds -> IMAD (FMA pipe)

struct Keys { uint32_t k1[LL], k2[LL]; };

// ---------------------------------------------------------------------------
// Threefry-2x32, 20 rounds — canonical, matches JAX's threefry2x32 primitive.
// tf_bal: rotations via SHF (ALU pipe); adds via IMAD with runtime 1 (FMA).
//   Takes the pre-added x1 init (c0 + g*256 + k2, formed on the FMA pipe by
//   the caller) so the per-element counter add stays off the ALU pipe.
// tf_plain: plain form for the rare exact-refine path. Identical bits.
// ---------------------------------------------------------------------------
#define RS(r) { x0 += x1; x1 = __funnelshift_l(x1, x1, (r)) ^ x0; }

__device__ __forceinline__ uint32_t tf_bal(uint32_t x1init, uint32_t one,
    uint32_t k1, uint32_t k2, uint32_t k3,
    uint32_t k31, uint32_t k12, uint32_t k23, uint32_t k34, uint32_t k15) {
#define RADD(a,b) ((a) * one + (b))
#define RND(r) { x0 = RADD(x1, x0); x1 = __funnelshift_l(x1, x1, (r)) ^ x0; }
  uint32_t x0 = k1, x1 = x1init;
  RND(13) RND(15) RND(26) RND(6)
  x0 = RADD(k2, x0); x1 = RADD(k31, x1);
  RND(17) RND(29) RND(16) RND(24)
  x0 = RADD(k3, x0); x1 = RADD(k12, x1);
  RND(13) RND(15) RND(26) RND(6)
  x0 = RADD(k1, x0); x1 = RADD(k23, x1);
  RND(17) RND(29) RND(16) RND(24)
  x0 = RADD(k2, x0); x1 = RADD(k34, x1);
  RND(13) RND(15) RND(26) RND(6)
  x0 = RADD(k3, x0); x1 = RADD(k15, x1);
#undef RND
#undef RADD
  return x0 ^ x1;
}

__device__ uint32_t tf_plain(uint32_t ctr, uint32_t k1, uint32_t k2, uint32_t k3) {
  uint32_t x0 = k1, x1 = ctr + k2;
  RS(13) RS(15) RS(26) RS(6)
  x0 += k2; x1 += k3 + 1u;
  RS(17) RS(29) RS(16) RS(24)
  x0 += k3; x1 += k1 + 2u;
  RS(13) RS(15) RS(26) RS(6)
  x0 += k1; x1 += k2 + 3u;
  RS(17) RS(29) RS(16) RS(24)
  x0 += k2; x1 += k3 + 4u;
  RS(13) RS(15) RS(26) RS(6)
  x0 += k3; x1 += k1 + 5u;
  return x0 ^ x1;
}

static void host_threefry(uint32_t k1, uint32_t k2, uint32_t& x0, uint32_t& x1) {
  uint32_t k3 = k1 ^ k2 ^ 0x1BD11BDAu;
  x0 += k1; x1 += k2;
#define TFRH(r) { x0 += x1; x1 = (x1 << (r)) | (x1 >> (32 - (r))); x1 ^= x0; }
  TFRH(13) TFRH(15) TFRH(26) TFRH(6)
  x0 += k2; x1 += k3 + 1u;
  TFRH(17) TFRH(29) TFRH(16) TFRH(24)
  x0 += k3; x1 += k1 + 2u;
  TFRH(13) TFRH(15) TFRH(26) TFRH(6)
  x0 += k1; x1 += k2 + 3u;
  TFRH(17) TFRH(29) TFRH(16) TFRH(24)
  x0 += k2; x1 += k3 + 4u;
  TFRH(13) TFRH(15) TFRH(26) TFRH(6)
  x0 += k3; x1 += k1 + 5u;
#undef TFRH
}

__device__ __forceinline__ float sigmoidf_(float x) {
  if (x >= 0.f) { float z = expf(-x); return 1.f / (1.f + z); }
  float z = expf(x); return z / (1.f + z);
}

// Exact reference value, byte-identical to the validated pipeline:
//   v = log(p + 1e-9) + (-log(-log(max(tiny, f))))
__device__ __noinline__ float refine_v(uint32_t ctr, float pj,
                                       uint32_t k1, uint32_t k2, uint32_t k3) {
  uint32_t bits = tf_plain(ctr, k1, k2, k3);
  float f = __uint_as_float((bits >> 9) | 0x3f800000u) - 1.0f;
  float u = fmaxf(1.17549435e-38f, f);
  float g = -logf(-logf(u));
  return logf(pj + 1e-9f) + g;
}

// Block-wide argmax with first-index tie rule (fallback path only).
__device__ __forceinline__ void block_argmax(float bv, int bj, int tid,
                                             float* sv, int* sj,
                                             float* s_bv, int* s_bj) {
  for (int off = 16; off; off >>= 1) {
    float ov = __shfl_down_sync(0xffffffffu, bv, off);
    int   oj = __shfl_down_sync(0xffffffffu, bj, off);
    if (ov > bv || (ov == bv && oj < bj)) { bv = ov; bj = oj; }
  }
  __syncthreads();
  if ((tid & 31) == 0) { sv[tid >> 5] = bv; sj[tid >> 5] = bj; }
  __syncthreads();
  if (tid == 0) {
    float xb = sv[0]; int xj = sj[0];
    for (int w = 1; w < 8; w++)
      if (sv[w] > xb || (sv[w] == xb && sj[w] < xj)) { xb = sv[w]; xj = sj[w]; }
    *s_bv = xb; *s_bj = xj;
  }
  __syncthreads();
}

// ---------------------------------------------------------------------------
// Fused walk kernel: one block per (r,n) pair runs all 7 Gumbel-max steps.
// Pass 1: Threefry + integer threshold (ALU carries only SHF/LOP3/ISETP).
// Pass 2: warp 0 only — exact refine of <=64 compacted candidates.
// ---------------------------------------------------------------------------
__global__ void __launch_bounds__(256) walk_all_kernel(
    const float* __restrict__ prob, Keys ks) {
  __shared__ float sv[8];
  __shared__ int   sj[8];
  __shared__ float s_bv;
  __shared__ int   s_bj;
  __shared__ int   s_cnt;
  __shared__ int   s_cand[64];

  const uint32_t one = g_one;

  int p   = blockIdx.x;                  // r*N + n
  int tid = threadIdx.x;
  uint32_t base = (uint32_t)p << 12;     // p * NN
  int cur = p & (NN - 1);
  if (tid == 0) g_walk[0][p] = cur;

  for (int t = 1; t < LL; t++) {
    uint32_t k1 = ks.k1[t], k2 = ks.k2[t];
    uint32_t k3  = k1 ^ k2 ^ 0x1BD11BDAu;
    uint32_t k31 = k3 + 1u, k12 = k1 + 2u, k23 = k2 + 3u,
             k34 = k3 + 4u, k15 = k1 + 5u;
    const float* __restrict__ row = prob + (size_t)cur * NN;

    if (tid == 0) s_cnt = 0;
    __syncthreads();

    // Pass 1: Threefry + integer threshold. Candidate rate ~0.33%.
    // x1base = (base + tid) + k2; per-g init formed via IMAD-imm (FMA pipe).
    uint32_t x1base = (base + (uint32_t)tid) * one + k2;
#pragma unroll
    for (int g = 0; g < NN / 256; g++) {
      uint32_t x1i = ((uint32_t)(g * 256)) * one + x1base;
      uint32_t bits = tf_bal(x1i, one,
                             k1, k2, k3, k31, k12, k23, k34, k15);
      if (bits >= B0_BITS) {
        int slot = atomicAdd(&s_cnt, 1);
        if (slot < 64) s_cand[slot] = g * 256 + tid;
      }
    }
    __syncthreads();

    // Pass 2: warp 0 refines the compacted candidates (typically ~14).
    int ncand = s_cnt;
    if (tid < 32) {
      float bv = __int_as_float(0xff800000);   // -inf
      int   bj = 0x7fffffff;
      int nc = ncand < 64 ? ncand : 64;
      for (int s = tid; s < nc; s += 32) {
        int j = s_cand[s];
        float v = refine_v(base + (uint32_t)j, __ldg(row + j), k1, k2, k3);
        if (v > bv || (v == bv && j < bj)) { bv = v; bj = j; }
      }
      for (int off = 16; off; off >>= 1) {
        float ov = __shfl_down_sync(0xffffffffu, bv, off);
        int   oj = __shfl_down_sync(0xffffffffu, bj, off);
        if (ov > bv || (ov == bv && oj < bj)) { bv = ov; bj = oj; }
      }
      if (tid == 0) { s_bv = bv; s_bj = bj; }
    }
    __syncthreads();

    // Safety fallback: exact full-row scan (rare: ~0.1% of rows).
    if (ncand > 64 || !(s_bv >= VSAFE)) {
      float bv = __int_as_float(0xff800000);
      int   bj = 0x7fffffff;
#pragma unroll 4
      for (int g = 0; g < NN / 256; g++) {
        int j = g * 256 + tid;
        float v = refine_v(base + (uint32_t)j, __ldg(row + j), k1, k2, k3);
        if (v > bv || (v == bv && j < bj)) { bv = v; bj = j; }
      }
      block_argmax(bv, bj, tid, sv, sj, &s_bv, &s_bj);
    }

    cur = s_bj;
    if (tid == 0) g_walk[t][p] = cur;
    __syncthreads();
  }
}

// ---------------------------------------------------------------------------
// Trajectory recurrence: 4 warps/block (128 thr), 4 pairs per warp, grid 1024.
// Weights via __ldg (L1-resident broadcast). Lane owns h = {2*lane, 2*lane+1}
// so each k needs ONE LDG.64 of W1 (was two LDG.32). Per-(pair,h) fmaf chain
// over k unchanged -> bit-identical results.
// ---------------------------------------------------------------------------
__global__ void __launch_bounds__(128) rye_kernel(
    const float* __restrict__ inv_in, const float* __restrict__ eq_in,
    const float* __restrict__ W1, const float* __restrict__ b1,
    const float* __restrict__ W2, const float* __restrict__ b2,
    float* __restrict__ out) {
  __shared__ __align__(16) float sfT_all[4][FEAT * 4];   // [warp][k][p]
  __shared__ float seqh_all[4][192];                     // [warp][p][d*16+c]
  __shared__ float scoef_all[4][128];                    // [warp][p][o]
  __shared__ float seqin_all[4][16];                     // [warp][p][d]

  int tid  = threadIdx.x;
  int w    = tid >> 5;
  int lane = tid & 31;

  float* sfT   = sfT_all[w];
  float* seqh  = seqh_all[w];
  float* scoef = scoef_all[w];
  float* seqin = seqin_all[w];

  int pair0 = blockIdx.x * 16 + w * 4;

  for (int i = lane; i < 256; i += 32) sfT[256 + i] = 0.f;
  for (int i = lane; i < 192; i += 32) seqh[i] = 0.f;
  __syncwarp();

  const float2 bb  = __ldg((const float2*)(b1 + 2 * lane));  // bias for h=2l, 2l+1
  const float  b2v = __ldg(b2 + lane);

  const size_t EQ_BASE = (size_t)RR * LL * NN * HH;   // 8388608
  const int pl = lane & 3;
  const int kk = lane >> 2;

  for (int l = 0; l < LL; l++) {
    int nd = (lane < 4) ? g_walk[LL - 1 - l][pair0 + lane] : 0;
    int np = __shfl_sync(0xffffffffu, nd, pl);

#pragma unroll
    for (int j = 0; j < 8; j++) {
      int k = kk + 8 * j;
      sfT[4 * k + pl] = __ldg(inv_in + (size_t)np * FF + k);
    }
    if (lane < 12) {
      float e = 0.f;
      if (l > 0) {
        int prev = g_walk[LL - l][pair0 + pl];
        e = __ldg(eq_in + (size_t)np * 3 + kk) - __ldg(eq_in + (size_t)prev * 3 + kk);
      }
      seqin[pl * 4 + kk] = e;
    }
    if (lane < 16) {
#pragma unroll
      for (int p = 0; p < 4; p++) {
        float d0 = seqh[p * 48 + lane], d1 = seqh[p * 48 + 16 + lane],
              d2 = seqh[p * 48 + 32 + lane];
        sfT[4 * (128 + lane) + p] = d0 * d0 + d1 * d1 + d2 * d2;
      }
    }
    __syncwarp();

    // GEMV1 for 4 pairs: lane owns h = 2*lane (a0x) and h = 2*lane+1 (a1x).
    float a00 = 0.f, a01 = 0.f, a02 = 0.f, a03 = 0.f;
    float a10 = 0.f, a11 = 0.f, a12 = 0.f, a13 = 0.f;
#pragma unroll 4
    for (int k = 0; k < FEAT; k++) {
      float2 wv = __ldg((const float2*)(W1 + k * HH + 2 * lane));
      float4 f = *(const float4*)(sfT + 4 * k);
      a00 = fmaf(f.x, wv.x, a00); a10 = fmaf(f.x, wv.y, a10);
      a01 = fmaf(f.y, wv.x, a01); a11 = fmaf(f.y, wv.y, a11);
      a02 = fmaf(f.z, wv.x, a02); a12 = fmaf(f.z, wv.y, a12);
      a03 = fmaf(f.w, wv.x, a03); a13 = fmaf(f.w, wv.y, a13);
    }
    float H0[4], H1[4];
    H0[0] = tanhf(a00 + bb.x); H0[1] = tanhf(a01 + bb.x);
    H0[2] = tanhf(a02 + bb.x); H0[3] = tanhf(a03 + bb.x);
    H1[0] = tanhf(a10 + bb.y); H1[1] = tanhf(a11 + bb.y);
    H1[2] = tanhf(a12 + bb.y); H1[3] = tanhf(a13 + bb.y);
    __syncwarp();
    *(float4*)(sfT + 4 * (64 + 2 * lane))     = make_float4(H0[0], H0[1], H0[2], H0[3]);
    *(float4*)(sfT + 4 * (64 + 2 * lane + 1)) = make_float4(H1[0], H1[1], H1[2], H1[3]);
    __syncwarp();

    // GEMV2: coef[o=lane] for 4 pairs (reads h rows 64..127 sequentially).
    float c0 = 0.f, c1 = 0.f, c2 = 0.f, c3 = 0.f;
#pragma unroll 8
    for (int k = 0; k < HH; k++) {
      float wv = __ldg(W2 + k * (2 * CC) + lane);
      float4 h = *(const float4*)(sfT + 4 * (64 + k));
      c0 = fmaf(h.x, wv, c0); c1 = fmaf(h.y, wv, c1);
      c2 = fmaf(h.z, wv, c2); c3 = fmaf(h.w, wv, c3);
    }
    scoef[lane]      = c0 + b2v;
    scoef[32 + lane] = c1 + b2v;
    scoef[64 + lane] = c2 + b2v;
    scoef[96 + lane] = c3 + b2v;
    __syncwarp();

    // invariant outputs: one STG.64 per pair per lane (h = 2l, 2l+1)
#pragma unroll
    for (int p = 0; p < 4; p++) {
      int pr = pair0 + p; int r = pr >> 12; int n = pr & (NN - 1);
      size_t inv_off = (((size_t)r * LL + l) * NN + n) * HH;
      *(float2*)(out + inv_off + 2 * lane) = make_float2(H0[p], H1[p]);
    }
    if (lane < 16) {
#pragma unroll
      for (int p = 0; p < 4; p++) {
        float gate = sigmoidf_(scoef[p * 32 + lane]);
        float scl  = scoef[p * 32 + 16 + lane];
        float e0 = seqin[p * 4 + 0], e1 = seqin[p * 4 + 1], e2 = seqin[p * 4 + 2];
        float v0 = seqh[p * 48 + lane]      * gate + e0 * scl;
        float v1 = seqh[p * 48 + 16 + lane] * gate + e1 * scl;
        float v2 = seqh[p * 48 + 32 + lane] * gate + e2 * scl;
        seqh[p * 48 + lane] = v0; seqh[p * 48 + 16 + lane] = v1; seqh[p * 48 + 32 + lane] = v2;
        int pr = pair0 + p; int r = pr >> 12; int n = pr & (NN - 1);
        size_t eq_off = EQ_BASE + (((size_t)r * LL + l) * NN + n) * (3 * CC) + lane;
        out[eq_off]          = v0;
        out[eq_off + CC]     = v1;
        out[eq_off + 2 * CC] = v2;
      }
    }
    __syncwarp();
  }
}

// ---------------------------------------------------------------------------
extern "C" void kernel_launch(void* const* d_in, const int* in_sizes, int n_in,
                              void* d_out, int out_size) {
  const float* prob = (const float*)d_in[0];
  const float* inv  = (const float*)d_in[1];
  const float* eq   = (const float*)d_in[2];
  const float* W1   = (const float*)d_in[3];
  const float* b1   = (const float*)d_in[4];
  const float* W2   = (const float*)d_in[5];
  const float* b2   = (const float*)d_in[6];
  float* out = (float*)d_out;
  (void)in_sizes; (void)n_in; (void)out_size;

  // Step keys: subkey[t] = threefry2x32((0,42), (0, t-1))
  Keys ks;
  for (int t = 1; t < LL; t++) {
    uint32_t x0 = 0u, x1 = (uint32_t)(t - 1);
    host_threefry(0u, 42u, x0, x1);
    ks.k1[t] = x0; ks.k2[t] = x1;
  }
  ks.k1[0] = 0; ks.k2[0] = 0;

  walk_all_kernel<<<NPAIR, 256>>>(prob, ks);
  rye_kernel<<<NPAIR / 16, 128>>>(inv, eq, W1, b1, W2, b2, out);
}